// round 2
// baseline (speedup 1.0000x reference)
#include <cuda_runtime.h>
#include <math.h>

#define CIN    512
#define MAXB   131072
#define NTAB   550           // 10+20+...+100 quadrature points
#define LOG2E  1.4426950408889634f
#define EPSQ   1e-5f

// Scratch for per-row pre-activation logits (za, zb). Static __device__ array
// (no allocation allowed in kernel_launch).
__device__ float2 g_scratch[MAXB];

__device__ __forceinline__ float ex2f(float x) {
    float r;
    asm("ex2.approx.f32 %0, %1;" : "=f"(r) : "f"(x));
    return r;
}

// ---------------------------------------------------------------------------
// Kernel 1: dual GEMV. One warp per row; fully coalesced float4 loads of x.
// W_alpha/W_beta (2 KB each) stay hot in L1. Only the raw logits are stored;
// the expensive scalar epilogue (softplus + 3x lgammaf) is deferred to
// kernel 2 where it amortizes 32 rows/warp instead of 1 row/warp.
// ---------------------------------------------------------------------------
__global__ void __launch_bounds__(256)
gemv2_kernel(const float* __restrict__ x,
             const float* __restrict__ Wa, const float* __restrict__ ba,
             const float* __restrict__ Wb, const float* __restrict__ bb,
             int B)
{
    int warp = blockIdx.x * (blockDim.x >> 5) + (threadIdx.x >> 5);
    int lane = threadIdx.x & 31;
    if (warp >= B) return;

    const float4* xr = reinterpret_cast<const float4*>(x) + (size_t)warp * (CIN / 4);
    const float4* wa = reinterpret_cast<const float4*>(Wa);
    const float4* wb = reinterpret_cast<const float4*>(Wb);

    float sa = 0.f, sb = 0.f;
#pragma unroll
    for (int m = 0; m < 4; ++m) {
        float4 xv = __ldg(xr + lane + 32 * m);
        float4 av = __ldg(wa + lane + 32 * m);
        float4 bv = __ldg(wb + lane + 32 * m);
        sa = fmaf(xv.x, av.x, fmaf(xv.y, av.y, fmaf(xv.z, av.z, fmaf(xv.w, av.w, sa))));
        sb = fmaf(xv.x, bv.x, fmaf(xv.y, bv.y, fmaf(xv.z, bv.z, fmaf(xv.w, bv.w, sb))));
    }
#pragma unroll
    for (int off = 16; off; off >>= 1) {
        sa += __shfl_xor_sync(0xffffffffu, sa, off);
        sb += __shfl_xor_sync(0xffffffffu, sb, off);
    }
    if (lane == 0)
        g_scratch[warp] = make_float2(sa + ba[0], sb + bb[0]);
}

// ---------------------------------------------------------------------------
// Kernel 2: per-row Beta quadrature. Thread-per-row. The 550 grid points'
// log(t)*log2e and log1p(-t)*log2e live in a shared table (row-independent),
// read by broadcast LDS. dx and exp(-lbeta) factors cancel in the final
// row normalization; -lbeta stays inside the exponent for fp32 range safety.
// ---------------------------------------------------------------------------
__global__ void __launch_bounds__(256)
beta_probs_kernel(float* __restrict__ out, int B)
{
    __shared__ float2 tab[NTAB];
    for (int k = threadIdx.x; k < NTAB; k += blockDim.x) {
        // locate grid g (0-based): grid g has 10*(g+1) points at offset 5g(g+1)
        int g = 0, off = 0;
        while (k >= off + 10 * (g + 1)) { off += 10 * (g + 1); ++g; }
        int n = 10 * (g + 1);
        int j = k - off;
        float bthr = 0.1f * (float)(g + 1);
        float step = (bthr - 2.f * EPSQ) / (float)(n - 1);
        float t = EPSQ + step * (float)j;
        tab[k] = make_float2(logf(t) * LOG2E, log1pf(-t) * LOG2E);
    }
    __syncthreads();

    int row = blockIdx.x * blockDim.x + threadIdx.x;
    if (row >= B) return;

    float2 z = g_scratch[row];
    float za = z.x, zb = z.y;
    // numerically stable softplus, matching jax.nn.softplus = logaddexp(z, 0)
    float spa = (za > 0.f) ? (za + log1pf(expf(-za))) : log1pf(expf(za));
    float spb = (zb > 0.f) ? (zb + log1pf(expf(-zb))) : log1pf(expf(zb));
    float alpha = fminf(1.f + spa, 100.f);
    float beta  = fminf(1.f + spb, 100.f);
    float lb = lgammaf(alpha) + lgammaf(beta) - lgammaf(alpha + beta);

    float a1 = alpha - 1.f;
    float b1 = beta - 1.f;
    float c  = -lb * LOG2E;

    float cdf[10];
    int off = 0;
#pragma unroll
    for (int g = 0; g < 10; ++g) {
        int n = 10 * (g + 1);        // compile-time after unroll
        float s = 0.f;
#pragma unroll 5
        for (int k = 0; k < n; ++k) {
            float2 uv = tab[off + k];
            s += ex2f(fmaf(a1, uv.x, fmaf(b1, uv.y, c)));
        }
        cdf[g] = s;
        off += n;
    }

    float pr[10];
    float prev = 0.f;
#pragma unroll
    for (int g = 0; g < 10; ++g) { pr[g] = cdf[g] - prev; prev = cdf[g]; }
    float inv = 1.f / cdf[9];        // total mass = cdf[9] (telescoping sum)

    float* o = out + (size_t)row * 10;
#pragma unroll
    for (int g = 0; g < 10; ++g) o[g] = pr[g] * inv;
}

// ---------------------------------------------------------------------------
extern "C" void kernel_launch(void* const* d_in, const int* in_sizes, int n_in,
                              void* d_out, int out_size)
{
    const float* x  = (const float*)d_in[0];
    const float* Wa = (const float*)d_in[1];
    const float* ba = (const float*)d_in[2];
    const float* Wb = (const float*)d_in[3];
    const float* bb = (const float*)d_in[4];

    int B = in_sizes[0] / CIN;
    if (B > MAXB) B = MAXB;

    int blocks1 = (B + 7) / 8;          // 8 warps (rows) per 256-thread block
    gemv2_kernel<<<blocks1, 256>>>(x, Wa, ba, Wb, bb, B);

    int blocks2 = (B + 255) / 256;
    beta_probs_kernel<<<blocks2, 256>>>((float*)d_out, B);
}

// round 3
// speedup vs baseline: 1.0082x; 1.0082x over previous
#include <cuda_runtime.h>
#include <math.h>

#define CIN     512
#define NTAB    550            // 10+20+...+100 quadrature points
#define LOG2E   1.4426950408889634f
#define EPSQ    1e-5f
#define ROWS_PB 256            // rows per block == threads per block

__device__ __forceinline__ float ex2f(float x) {
    float r;
    asm("ex2.approx.f32 %0, %1;" : "=f"(r) : "f"(x));
    return r;
}

// ---------------------------------------------------------------------------
// Fused kernel. Each 256-thread block owns 256 rows.
//   Phase 1 (memory-bound): 8 warps x 32 rows, warp-per-row dual GEMV.
//   Phase 2 (MUFU-bound):   thread-per-row Beta quadrature over a shared
//                           550-entry (log t, log1p(-t)) table.
// Different blocks are in different phases concurrently, so DRAM traffic of
// phase 1 overlaps the exp-heavy phase 2 chip-wide: total ~= max(mem, mufu).
// ---------------------------------------------------------------------------
__global__ void __launch_bounds__(ROWS_PB)
fused_beta_kernel(const float* __restrict__ x,
                  const float* __restrict__ Wa, const float* __restrict__ ba,
                  const float* __restrict__ Wb, const float* __restrict__ bb,
                  float* __restrict__ out, int B)
{
    __shared__ float2 tab[NTAB];       // (log t, log1p(-t)) * log2e
    __shared__ float2 zrow[ROWS_PB];   // per-row raw logits (za, zb)

    const int tid  = threadIdx.x;
    const int lane = tid & 31;
    const int wid  = tid >> 5;
    const int rbase = blockIdx.x * ROWS_PB;

    // ---- build quadrature table (row-independent; ~2-3 logf per thread) ----
    for (int k = tid; k < NTAB; k += ROWS_PB) {
        int g = 0, off = 0;                       // grid g: 10(g+1) pts @ off
        while (k >= off + 10 * (g + 1)) { off += 10 * (g + 1); ++g; }
        int n = 10 * (g + 1);
        int j = k - off;
        float bthr = 0.1f * (float)(g + 1);
        float step = (bthr - 2.f * EPSQ) / (float)(n - 1);
        float t = fmaf(step, (float)j, EPSQ);
        tab[k] = make_float2(logf(t) * LOG2E, log1pf(-t) * LOG2E);
    }

    // ---- phase 1: dual GEMV, warp-per-row, 32 rows per warp ----
    {
        const float4* wa4 = reinterpret_cast<const float4*>(Wa);
        const float4* wb4 = reinterpret_cast<const float4*>(Wb);
        // each lane's slice of the weight vectors stays in L1 across rows
        for (int r = 0; r < 32; ++r) {
            int row = rbase + wid * 32 + r;
            const float4* xr = reinterpret_cast<const float4*>(x)
                             + (size_t)row * (CIN / 4);
            float sa = 0.f, sb = 0.f;
#pragma unroll
            for (int m = 0; m < 4; ++m) {
                float4 xv = __ldcs(xr + lane + 32 * m);   // streaming, no reuse
                float4 av = __ldg(wa4 + lane + 32 * m);
                float4 bv = __ldg(wb4 + lane + 32 * m);
                sa = fmaf(xv.x, av.x, fmaf(xv.y, av.y,
                     fmaf(xv.z, av.z, fmaf(xv.w, av.w, sa))));
                sb = fmaf(xv.x, bv.x, fmaf(xv.y, bv.y,
                     fmaf(xv.z, bv.z, fmaf(xv.w, bv.w, sb))));
            }
#pragma unroll
            for (int off = 16; off; off >>= 1) {
                sa += __shfl_xor_sync(0xffffffffu, sa, off);
                sb += __shfl_xor_sync(0xffffffffu, sb, off);
            }
            if (lane == 0)
                zrow[wid * 32 + r] = make_float2(sa + ba[0], sb + bb[0]);
        }
    }
    __syncthreads();

    // ---- phase 2: thread-per-row quadrature ----
    int row = rbase + tid;
    if (row >= B) return;

    float za = zrow[tid].x, zb = zrow[tid].y;
    // stable softplus == jax.nn.softplus
    float spa = (za > 0.f) ? (za + log1pf(expf(-za))) : log1pf(expf(za));
    float spb = (zb > 0.f) ? (zb + log1pf(expf(-zb))) : log1pf(expf(zb));
    float alpha = fminf(1.f + spa, 100.f);
    float beta  = fminf(1.f + spb, 100.f);
    float lb = lgammaf(alpha) + lgammaf(beta) - lgammaf(alpha + beta);

    const float a1 = alpha - 1.f;
    const float b1 = beta - 1.f;
    const float c  = -lb * LOG2E;     // dx and exp(-lbeta) scale cancels in
                                      // normalization; keep -lbeta for range

    float cdf[10];
    const float2* tp = tab;           // pointer-walk: reg+imm LDS, 1 IADD/10
#pragma unroll
    for (int g = 0; g < 10; ++g) {
        const int n = 10 * (g + 1);
        float s = 0.f;
#pragma unroll 10
        for (int k = 0; k < n; ++k) {
            float2 uv = tp[k];
            s += ex2f(fmaf(a1, uv.x, fmaf(b1, uv.y, c)));
        }
        cdf[g] = s;
        tp += n;
    }

    float inv = 1.f / cdf[9];          // telescoping total mass
    float* o = out + (size_t)row * 10;
    float prev = 0.f;
#pragma unroll
    for (int g = 0; g < 10; ++g) {
        o[g] = (cdf[g] - prev) * inv;
        prev = cdf[g];
    }
}

// ---------------------------------------------------------------------------
extern "C" void kernel_launch(void* const* d_in, const int* in_sizes, int n_in,
                              void* d_out, int out_size)
{
    const float* x  = (const float*)d_in[0];
    const float* Wa = (const float*)d_in[1];
    const float* ba = (const float*)d_in[2];
    const float* Wb = (const float*)d_in[3];
    const float* bb = (const float*)d_in[4];

    int B = in_sizes[0] / CIN;
    int blocks = (B + ROWS_PB - 1) / ROWS_PB;
    fused_beta_kernel<<<blocks, ROWS_PB>>>(x, Wa, ba, Wb, bb, (float*)d_out, B);
}